// round 2
// baseline (speedup 1.0000x reference)
#include <cuda_runtime.h>
#include <math.h>

#define Bb 1024
#define Nn 11
#define Ff 512
#define ZI 10
#define PPF 66
#define R0 (Bb*PPF)     /* 67584 rows, full pass */
#define R1 (Bb*Nn)      /* 11264 rows, incremental pass */
#define G3 1536

#define BM 128
#define BN 128
#define BK 16
#define TM 8
#define TN 8
#define NTHR 256

// pair (i,j), i<=j, 66 pairs for N=11
__constant__ int c_pi[66] = {
  0,0,0,0,0,0,0,0,0,0,0,
  1,1,1,1,1,1,1,1,1,1,
  2,2,2,2,2,2,2,2,2,
  3,3,3,3,3,3,3,3,
  4,4,4,4,4,4,4,
  5,5,5,5,5,5,
  6,6,6,6,6,
  7,7,7,7,
  8,8,8,
  9,9,
  10};
__constant__ int c_pj[66] = {
  0,1,2,3,4,5,6,7,8,9,10,
  1,2,3,4,5,6,7,8,9,10,
  2,3,4,5,6,7,8,9,10,
  3,4,5,6,7,8,9,10,
  4,5,6,7,8,9,10,
  5,6,7,8,9,10,
  6,7,8,9,10,
  7,8,9,10,
  8,9,10,
  9,10,
  10};

// scratch (static device globals; no runtime allocation)
__device__ float g_H1[R0 * Ff];      // 138 MB, layer-1 activations
__device__ float g_colA[Bb * Ff];
__device__ float g_colB[Bb * Ff];
__device__ float g_az[Bb * 12];      // [0..10]=a_z, [11]=a_z[zidx]
__device__ float g_mb[Bb * Ff];      // m_base
__device__ float g_gi[Bb * G3];
__device__ float g_gh[Bb * G3];

__device__ __forceinline__ float* colptr(int sel) {
    return sel ? g_colB : g_colA;
}

// ---------------------------------------------------------------------------
// K0: init colA = node_features[:, zidx, :]
__global__ void k_init(const float* __restrict__ nf)
{
    int idx = blockIdx.x * 256 + threadIdx.x;   // Bb*Ff total
    int b = idx >> 9, f = idx & 511;
    g_colA[idx] = nf[(b * Nn + ZI) * Ff + f];
}

// ---------------------------------------------------------------------------
// K1: H1 = relu( E @ W1^T + b1 ),  E[r][f] = x_i[f]*x_j[f] generated on the fly
__global__ __launch_bounds__(NTHR)
void k_mlp1(const float* __restrict__ nf, int colsel,
            const float* __restrict__ W1, const float* __restrict__ b1,
            int ppb, int full)
{
    __shared__ __align__(16) float As[BK][BM];
    __shared__ __align__(16) float Bs[BK][BN];
    __shared__ const float* rpi[BM];
    __shared__ const float* rpj[BM];

    const int tid = threadIdx.x;
    const int rb = blockIdx.x, cb = blockIdx.y;
    const float* col = colptr(colsel);

    if (tid < BM) {
        int gr = rb * BM + tid;
        int b = gr / ppb, p = gr - b * ppb;
        int i, j;
        if (full) { i = c_pi[p]; j = c_pj[p]; } else { i = p; j = ZI; }
        rpi[tid] = (i == ZI) ? (col + b * Ff) : (nf + (b * Nn + i) * Ff);
        rpj[tid] = (j == ZI) ? (col + b * Ff) : (nf + (b * Nn + j) * Ff);
    }
    __syncthreads();

    const int r  = tid >> 1;
    const int fq = (tid & 1) * 2;
    const float* pi = rpi[r];
    const float* pj = rpj[r];
    const float* wp = W1 + (cb * BN + r) * Ff;

    float acc[TM][TN];
#pragma unroll
    for (int a = 0; a < TM; a++)
#pragma unroll
        for (int c = 0; c < TN; c++) acc[a][c] = 0.f;

    const int m0 = (tid >> 4) * TM, n0 = (tid & 15) * TN;

    for (int kt = 0; kt < Ff; kt += BK) {
#pragma unroll
        for (int q = 0; q < 2; q++) {
            int slot = fq + q;
            float4 av = *(const float4*)(pi + kt + slot * 4);
            float4 cv = *(const float4*)(pj + kt + slot * 4);
            As[slot * 4 + 0][r] = av.x * cv.x;
            As[slot * 4 + 1][r] = av.y * cv.y;
            As[slot * 4 + 2][r] = av.z * cv.z;
            As[slot * 4 + 3][r] = av.w * cv.w;
            float4 wv = *(const float4*)(wp + kt + slot * 4);
            Bs[slot * 4 + 0][r] = wv.x;
            Bs[slot * 4 + 1][r] = wv.y;
            Bs[slot * 4 + 2][r] = wv.z;
            Bs[slot * 4 + 3][r] = wv.w;
        }
        __syncthreads();
#pragma unroll
        for (int kk = 0; kk < BK; kk++) {
            float af[TM], bf[TN];
            *(float4*)&af[0] = *(const float4*)&As[kk][m0];
            *(float4*)&af[4] = *(const float4*)&As[kk][m0 + 4];
            *(float4*)&bf[0] = *(const float4*)&Bs[kk][n0];
            *(float4*)&bf[4] = *(const float4*)&Bs[kk][n0 + 4];
#pragma unroll
            for (int a = 0; a < TM; a++)
#pragma unroll
                for (int c = 0; c < TN; c++)
                    acc[a][c] += af[a] * bf[c];
        }
        __syncthreads();
    }

    const int ty = tid >> 4, tx = tid & 15;
    const int row0 = rb * BM + ty * TM;
    const int g0 = cb * BN + tx * TN;
    float bb[TN];
#pragma unroll
    for (int c = 0; c < TN; c++) bb[c] = b1[g0 + c];
#pragma unroll
    for (int a = 0; a < TM; a++) {
        float o[TN];
#pragma unroll
        for (int c = 0; c < TN; c++) {
            float v = acc[a][c] + bb[c];
            o[c] = v > 0.f ? v : 0.f;
        }
        *(float4*)&g_H1[(row0 + a) * Ff + g0]     = *(float4*)&o[0];
        *(float4*)&g_H1[(row0 + a) * Ff + g0 + 4] = *(float4*)&o[4];
    }
}

// ---------------------------------------------------------------------------
// K2: adj[r] = sum_g wout[g]*relu( (H1 @ W2^T)[r][g] + b2[g] ) + bout
//     block covers 128 rows x all 512 g (4 serial chunks) -> no atomics
__global__ __launch_bounds__(NTHR)
void k_mlp2(const float* __restrict__ W2, const float* __restrict__ b2,
            const float* __restrict__ wout, const float* __restrict__ boutp,
            float* __restrict__ adj, int ppb, int full)
{
    __shared__ __align__(16) float As[BK][BM];
    __shared__ __align__(16) float Bs[BK][BN];
    __shared__ float red[BM][17];

    const int tid = threadIdx.x;
    const int rb = blockIdx.x;
    const int r  = tid >> 1;
    const int fq = (tid & 1) * 2;
    const int ty = tid >> 4, tx = tid & 15;
    const int m0 = ty * TM, n0 = tx * TN;

    const float* ap = g_H1 + (rb * BM + r) * Ff;

    float rowpart[TM];
#pragma unroll
    for (int a = 0; a < TM; a++) rowpart[a] = 0.f;

    for (int gc = 0; gc < 4; gc++) {
        const float* wp = W2 + (gc * BN + r) * Ff;
        float acc[TM][TN];
#pragma unroll
        for (int a = 0; a < TM; a++)
#pragma unroll
            for (int c = 0; c < TN; c++) acc[a][c] = 0.f;

        for (int kt = 0; kt < Ff; kt += BK) {
#pragma unroll
            for (int q = 0; q < 2; q++) {
                int slot = fq + q;
                float4 av = *(const float4*)(ap + kt + slot * 4);
                As[slot * 4 + 0][r] = av.x;
                As[slot * 4 + 1][r] = av.y;
                As[slot * 4 + 2][r] = av.z;
                As[slot * 4 + 3][r] = av.w;
                float4 wv = *(const float4*)(wp + kt + slot * 4);
                Bs[slot * 4 + 0][r] = wv.x;
                Bs[slot * 4 + 1][r] = wv.y;
                Bs[slot * 4 + 2][r] = wv.z;
                Bs[slot * 4 + 3][r] = wv.w;
            }
            __syncthreads();
#pragma unroll
            for (int kk = 0; kk < BK; kk++) {
                float af[TM], bf[TN];
                *(float4*)&af[0] = *(const float4*)&As[kk][m0];
                *(float4*)&af[4] = *(const float4*)&As[kk][m0 + 4];
                *(float4*)&bf[0] = *(const float4*)&Bs[kk][n0];
                *(float4*)&bf[4] = *(const float4*)&Bs[kk][n0 + 4];
#pragma unroll
                for (int a = 0; a < TM; a++)
#pragma unroll
                    for (int c = 0; c < TN; c++)
                        acc[a][c] += af[a] * bf[c];
            }
            __syncthreads();
        }
        const int g0 = gc * BN + n0;
#pragma unroll
        for (int a = 0; a < TM; a++)
#pragma unroll
            for (int c = 0; c < TN; c++) {
                float v = acc[a][c] + b2[g0 + c];
                v = v > 0.f ? v : 0.f;
                rowpart[a] += v * wout[g0 + c];
            }
    }

#pragma unroll
    for (int a = 0; a < TM; a++) red[m0 + a][tx] = rowpart[a];
    __syncthreads();

    if (tid < BM) {
        float s = 0.f;
#pragma unroll
        for (int x = 0; x < 16; x++) s += red[tid][x];
        s += boutp[0];
        int gr = rb * BM + tid;
        int b = gr / ppb, p = gr - b * ppb;
        int i, j;
        if (full) { i = c_pi[p]; j = c_pj[p]; } else { i = p; j = ZI; }
        adj[b * 121 + i * 11 + j] = s;
        adj[b * 121 + j * 11 + i] = s;
    }
}

// ---------------------------------------------------------------------------
// K3: a_z = softmax(adj[b, zidx, :]) ; az[b*12+11] = a_z[zidx]
__global__ void k_softmax(const float* __restrict__ adj)
{
    int b = blockIdx.x;
    int t = threadIdx.x;   // 32 threads
    float v = (t < 11) ? adj[b * 121 + ZI * 11 + t] : -1e30f;
    float m = v;
#pragma unroll
    for (int o = 16; o > 0; o >>= 1) m = fmaxf(m, __shfl_xor_sync(0xffffffffu, m, o));
    float e = (t < 11) ? expf(v - m) : 0.f;
    float s = e;
#pragma unroll
    for (int o = 16; o > 0; o >>= 1) s += __shfl_xor_sync(0xffffffffu, s, o);
    float a = e / s;
    if (t < 11) g_az[b * 12 + t] = a;
    if (t == ZI) g_az[b * 12 + 11] = a;
}

// ---------------------------------------------------------------------------
// K4: m_base[b][f] = sum_{j != zidx} a_z[b][j] * nf[b][j][f]
__global__ void k_mbase(const float* __restrict__ nf)
{
    int b = blockIdx.x;
    int f = blockIdx.y * 128 + threadIdx.x;
    float s = 0.f;
#pragma unroll
    for (int j = 0; j < 10; j++)
        s += g_az[b * 12 + j] * nf[(b * Nn + j) * Ff + f];
    g_mb[b * Ff + f] = s;
}

// ---------------------------------------------------------------------------
// K5: gi = m_z @ W_ih^T ; gh = cur @ W_hh^T   (blockIdx.z selects)
//     m_z[b][f] = m_base[b][f] + a_z[b][zidx]*cur[b][f]
__global__ __launch_bounds__(NTHR)
void k_gru_mm(int colsel,
              const float* __restrict__ Wih, const float* __restrict__ Whh)
{
    __shared__ __align__(16) float As[BK][BM];
    __shared__ __align__(16) float Bs[BK][BN];
    __shared__ float azs[BM];

    const int tid = threadIdx.x;
    const int rb = blockIdx.x, cb = blockIdx.y, wh = blockIdx.z;
    const float* cur = colptr(colsel);

    if (tid < BM) azs[tid] = g_az[(rb * BM + tid) * 12 + 11];
    __syncthreads();

    const float* W = wh ? Whh : Wih;
    float* out = wh ? g_gh : g_gi;

    const int r  = tid >> 1;
    const int fq = (tid & 1) * 2;
    const int brow = rb * BM + r;
    const float* cp = cur + brow * Ff;
    const float* mp = g_mb + brow * Ff;
    const float azz = azs[r];
    const float* wp = W + (cb * BN + r) * Ff;
    const int m0 = (tid >> 4) * TM, n0 = (tid & 15) * TN;

    float acc[TM][TN];
#pragma unroll
    for (int a = 0; a < TM; a++)
#pragma unroll
        for (int c = 0; c < TN; c++) acc[a][c] = 0.f;

    for (int kt = 0; kt < Ff; kt += BK) {
#pragma unroll
        for (int q = 0; q < 2; q++) {
            int slot = fq + q;
            float4 cv = *(const float4*)(cp + kt + slot * 4);
            float4 v;
            if (wh) {
                v = cv;
            } else {
                float4 mv = *(const float4*)(mp + kt + slot * 4);
                v.x = mv.x + azz * cv.x;
                v.y = mv.y + azz * cv.y;
                v.z = mv.z + azz * cv.z;
                v.w = mv.w + azz * cv.w;
            }
            As[slot * 4 + 0][r] = v.x;
            As[slot * 4 + 1][r] = v.y;
            As[slot * 4 + 2][r] = v.z;
            As[slot * 4 + 3][r] = v.w;
            float4 wv = *(const float4*)(wp + kt + slot * 4);
            Bs[slot * 4 + 0][r] = wv.x;
            Bs[slot * 4 + 1][r] = wv.y;
            Bs[slot * 4 + 2][r] = wv.z;
            Bs[slot * 4 + 3][r] = wv.w;
        }
        __syncthreads();
#pragma unroll
        for (int kk = 0; kk < BK; kk++) {
            float af[TM], bf[TN];
            *(float4*)&af[0] = *(const float4*)&As[kk][m0];
            *(float4*)&af[4] = *(const float4*)&As[kk][m0 + 4];
            *(float4*)&bf[0] = *(const float4*)&Bs[kk][n0];
            *(float4*)&bf[4] = *(const float4*)&Bs[kk][n0 + 4];
#pragma unroll
            for (int a = 0; a < TM; a++)
#pragma unroll
                for (int c = 0; c < TN; c++)
                    acc[a][c] += af[a] * bf[c];
        }
        __syncthreads();
    }

    const int ty = tid >> 4, tx = tid & 15;
    const int row0 = rb * BM + ty * TM;
    const int g0 = cb * BN + tx * TN;
#pragma unroll
    for (int a = 0; a < TM; a++) {
        *(float4*)&out[(row0 + a) * G3 + g0]     = *(float4*)&acc[a][0];
        *(float4*)&out[(row0 + a) * G3 + g0 + 4] = *(float4*)&acc[a][4];
    }
}

// ---------------------------------------------------------------------------
// K6: GRU gates elementwise; reads cur=colptr(sel), writes colptr(1-sel)
__global__ void k_gate(int colsel)
{
    int idx = blockIdx.x * 256 + threadIdx.x;  // Bb*Ff
    int b = idx >> 9, f = idx & 511;
    const float* cur = colptr(colsel);
    float* nxt = colptr(1 - colsel);
    const float* gib = g_gi + b * G3;
    const float* ghb = g_gh + b * G3;
    float ir = gib[f],        hr = ghb[f];
    float iz = gib[512 + f],  hz = ghb[512 + f];
    float in_ = gib[1024 + f], hn = ghb[1024 + f];
    float rr = 1.f / (1.f + expf(-(ir + hr)));
    float zz = 1.f / (1.f + expf(-(iz + hz)));
    float nn = tanhf(in_ + rr * hn);
    float h = cur[idx];
    nxt[idx] = (1.f - zz) * nn + zz * h;
}

// ---------------------------------------------------------------------------
// K7: copy final col to output
__global__ void k_copy(int colsel, float* __restrict__ dst)
{
    int idx = blockIdx.x * 256 + threadIdx.x;
    dst[idx] = colptr(colsel)[idx];
}

// ---------------------------------------------------------------------------
extern "C" void kernel_launch(void* const* d_in, const int* in_sizes, int n_in,
                              void* d_out, int out_size)
{
    const float* nf  = (const float*)d_in[0];
    const float* W1  = (const float*)d_in[1];
    const float* b1  = (const float*)d_in[2];
    const float* W2  = (const float*)d_in[3];
    const float* b2  = (const float*)d_in[4];
    const float* wo  = (const float*)d_in[5];
    const float* bo  = (const float*)d_in[6];
    const float* Wih = (const float*)d_in[7];
    const float* Whh = (const float*)d_in[8];

    float* adj    = (float*)d_out;             // 1024*121 floats
    float* colout = (float*)d_out + Bb * 121;  // 1024*512 floats

    k_init<<<(Bb * Ff) / 256, 256>>>(nf);

    int sel = 0;  // cur = colA

    for (int t = 0; t < 3; t++) {
        if (t == 0) {
            k_mlp1<<<dim3(R0 / BM, Ff / BN), NTHR>>>(nf, sel, W1, b1, PPF, 1);
            k_mlp2<<<R0 / BM, NTHR>>>(W2, b2, wo, bo, adj, PPF, 1);
        } else {
            k_mlp1<<<dim3(R1 / BM, Ff / BN), NTHR>>>(nf, sel, W1, b1, Nn, 0);
            k_mlp2<<<R1 / BM, NTHR>>>(W2, b2, wo, bo, adj, Nn, 0);
        }
        k_softmax<<<Bb, 32>>>(adj);
        k_mbase<<<dim3(Bb, Ff / 128), 128>>>(nf);
        for (int s = 0; s < 3; s++) {
            k_gru_mm<<<dim3(Bb / BM, G3 / BN, 2), NTHR>>>(sel, Wih, Whh);
            k_gate<<<(Bb * Ff) / 256, 256>>>(sel);
            sel = 1 - sel;
        }
    }
    k_copy<<<(Bb * Ff) / 256, 256>>>(sel, colout);
}

// round 5
// speedup vs baseline: 1.5816x; 1.5816x over previous
#include <cuda_runtime.h>
#include <cuda_bf16.h>
#include <math.h>
#include <stdint.h>

#define Bb 1024
#define Nn 11
#define Ff 512
#define ZI 10
#define PPF 66
#define R0 (Bb*PPF)
#define R1 (Bb*Nn)
#define G3 1536

#define KC 32
#define NCHUNK (Ff/KC)      /* 16 */
#define SSTRIDE 40          /* bf16 elems per smem row (32 data + 8 pad) */
/* byte offsets inside smb (each plane = 128*40*2 = 10240 B) */
#define OF_AHI 0
#define OF_ALO 10240
#define OF_BHI 20480
#define OF_BLO 30720

/* ------------------------------------------------------------------ */
__device__ __forceinline__ uint32_t smaddr(const void* p) {
    uint32_t a;
    asm("{ .reg .u64 t; cvta.to.shared.u64 t, %1; cvt.u32.u64 %0, t; }"
        : "=r"(a) : "l"(p));
    return a;
}
__device__ __forceinline__ void ldm4(uint32_t a, uint32_t* r) {
    asm volatile("ldmatrix.sync.aligned.m8n8.x4.shared.b16 {%0,%1,%2,%3}, [%4];"
                 : "=r"(r[0]), "=r"(r[1]), "=r"(r[2]), "=r"(r[3]) : "r"(a));
}
__device__ __forceinline__ void mma16816(float* d, const uint32_t* a, uint32_t b0, uint32_t b1) {
    asm volatile(
        "mma.sync.aligned.m16n8k16.row.col.f32.bf16.bf16.f32 "
        "{%0,%1,%2,%3},{%4,%5,%6,%7},{%8,%9},{%0,%1,%2,%3};"
        : "+f"(d[0]), "+f"(d[1]), "+f"(d[2]), "+f"(d[3])
        : "r"(a[0]), "r"(a[1]), "r"(a[2]), "r"(a[3]), "r"(b0), "r"(b1));
}
__device__ __forceinline__ void split1(float v, unsigned short& h, unsigned short& l) {
    __nv_bfloat16 bh = __float2bfloat16_rn(v);
    float r = v - __bfloat162float(bh);
    __nv_bfloat16 bl = __float2bfloat16_rn(r);
    h = *(unsigned short*)&bh;
    l = *(unsigned short*)&bl;
}
__device__ __forceinline__ void split4s(float4 v, uint2& hi, uint2& lo) {
    unsigned short h0,h1,h2,h3,l0,l1,l2,l3;
    split1(v.x,h0,l0); split1(v.y,h1,l1); split1(v.z,h2,l2); split1(v.w,h3,l3);
    hi.x = (uint32_t)h0 | ((uint32_t)h1 << 16);
    hi.y = (uint32_t)h2 | ((uint32_t)h3 << 16);
    lo.x = (uint32_t)l0 | ((uint32_t)l1 << 16);
    lo.y = (uint32_t)l2 | ((uint32_t)l3 << 16);
}

/* compute one 32-K chunk: 2 k16-steps, 3 split MMAs per (mt,nt) tile */
__device__ __forceinline__ void gemm_chunk(const unsigned short* smb, int wm, int wn,
                                           int lane, float acc[2][8][4])
{
    const uint32_t base = smaddr(smb);
    const int rsel = lane & 15;
    const int ksel = (lane >> 4) * 8;
#pragma unroll
    for (int s = 0; s < 2; s++) {
        uint32_t ah[2][4], al[2][4], bh[4][4], bl[4][4];
#pragma unroll
        for (int mt = 0; mt < 2; mt++) {
            uint32_t off = (uint32_t)((wm*32 + mt*16 + rsel) * SSTRIDE + s*16 + ksel) * 2;
            ldm4(base + OF_AHI + off, ah[mt]);
            ldm4(base + OF_ALO + off, al[mt]);
        }
#pragma unroll
        for (int np = 0; np < 4; np++) {
            uint32_t off = (uint32_t)((wn*64 + np*16 + rsel) * SSTRIDE + s*16 + ksel) * 2;
            ldm4(base + OF_BHI + off, bh[np]);
            ldm4(base + OF_BLO + off, bl[np]);
        }
#pragma unroll
        for (int mt = 0; mt < 2; mt++)
#pragma unroll
            for (int np = 0; np < 4; np++)
#pragma unroll
                for (int h = 0; h < 2; h++) {
                    const int nt = np*2 + h;
                    mma16816(acc[mt][nt], ah[mt], bh[np][h], bh[np][h+2]);
                    mma16816(acc[mt][nt], ah[mt], bl[np][h], bl[np][h+2]);
                    mma16816(acc[mt][nt], al[mt], bh[np][h], bh[np][h+2]);
                }
    }
}

/* ------------------------------------------------------------------ */
__constant__ int c_pi[66] = {
  0,0,0,0,0,0,0,0,0,0,0, 1,1,1,1,1,1,1,1,1,1, 2,2,2,2,2,2,2,2,2,
  3,3,3,3,3,3,3,3, 4,4,4,4,4,4,4, 5,5,5,5,5,5, 6,6,6,6,6, 7,7,7,7, 8,8,8, 9,9, 10};
__constant__ int c_pj[66] = {
  0,1,2,3,4,5,6,7,8,9,10, 1,2,3,4,5,6,7,8,9,10, 2,3,4,5,6,7,8,9,10,
  3,4,5,6,7,8,9,10, 4,5,6,7,8,9,10, 5,6,7,8,9,10, 6,7,8,9,10, 7,8,9,10, 8,9,10, 9,10, 10};

__device__ float g_H1[R0 * Ff];
__device__ float g_colA[Bb * Ff];
__device__ float g_colB[Bb * Ff];
__device__ float g_az[Bb * 12];
__device__ float g_mb[Bb * Ff];
__device__ float g_gi[Bb * G3];
__device__ float g_gh[Bb * G3];

__device__ __forceinline__ float* colptr(int sel) { return sel ? g_colB : g_colA; }

/* ------------------------------------------------------------------ */
__global__ void k_init(const float* __restrict__ nf)
{
    int idx = blockIdx.x * 256 + threadIdx.x;
    int b = idx >> 9, f = idx & 511;
    g_colA[idx] = nf[(b * Nn + ZI) * Ff + f];
}

/* ------------------------------------------------------------------ */
/* K1: H1 = relu(E @ W1^T + b1) */
__global__ __launch_bounds__(256)
void k_mlp1(const float* __restrict__ nf, int colsel,
            const float* __restrict__ W1, const float* __restrict__ b1,
            int ppb, int full)
{
    __shared__ __align__(16) unsigned short smb[20480];
    __shared__ const float* rpi[128];
    __shared__ const float* rpj[128];

    const int tid = threadIdx.x, wid = tid >> 5, lane = tid & 31;
    const int wm = wid & 3, wn = wid >> 2;
    const int rb = blockIdx.x, cb = blockIdx.y;
    const float* col = colptr(colsel);

    if (tid < 128) {
        int gr = rb * 128 + tid;
        int b = gr / ppb, p = gr - b * ppb;
        int i, j;
        if (full) { i = c_pi[p]; j = c_pj[p]; } else { i = p; j = ZI; }
        rpi[tid] = (i == ZI) ? (col + b * Ff) : (nf + (b * Nn + i) * Ff);
        rpj[tid] = (j == ZI) ? (col + b * Ff) : (nf + (b * Nn + j) * Ff);
    }
    __syncthreads();

    const float* wbase = W1 + (size_t)(cb * 128) * Ff;
    const int srow = tid >> 1;                     /* staging: 2 threads/row */
    const int sf4  = (tid & 1) * 4;                /* thread covers f4, f4+1..f4+3 */

    float4 pa[4], pb[4];
#pragma unroll
    for (int q = 0; q < 4; q++) {
        float4 av = *(const float4*)(rpi[srow] + (sf4 + q) * 4);
        float4 jv = *(const float4*)(rpj[srow] + (sf4 + q) * 4);
        pa[q] = make_float4(av.x*jv.x, av.y*jv.y, av.z*jv.z, av.w*jv.w);
        pb[q] = *(const float4*)(wbase + (size_t)srow * Ff + (sf4 + q) * 4);
    }

    float acc[2][8][4];
#pragma unroll
    for (int a = 0; a < 2; a++)
#pragma unroll
        for (int b = 0; b < 8; b++)
#pragma unroll
            for (int c = 0; c < 4; c++) acc[a][b][c] = 0.f;

    for (int c = 0; c < NCHUNK; c++) {
#pragma unroll
        for (int q = 0; q < 4; q++) {
            uint2 hi, lo;
            split4s(pa[q], hi, lo);
            int eo = srow * SSTRIDE + (sf4 + q) * 4;
            *(uint2*)((char*)smb + OF_AHI + eo*2) = hi;
            *(uint2*)((char*)smb + OF_ALO + eo*2) = lo;
            split4s(pb[q], hi, lo);
            *(uint2*)((char*)smb + OF_BHI + eo*2) = hi;
            *(uint2*)((char*)smb + OF_BLO + eo*2) = lo;
        }
        __syncthreads();
        if (c < NCHUNK - 1) {
            const int k0 = (c + 1) * KC;
#pragma unroll
            for (int q = 0; q < 4; q++) {
                float4 av = *(const float4*)(rpi[srow] + k0 + (sf4 + q) * 4);
                float4 jv = *(const float4*)(rpj[srow] + k0 + (sf4 + q) * 4);
                pa[q] = make_float4(av.x*jv.x, av.y*jv.y, av.z*jv.z, av.w*jv.w);
                pb[q] = *(const float4*)(wbase + (size_t)srow * Ff + k0 + (sf4 + q) * 4);
            }
        }
        gemm_chunk(smb, wm, wn, lane, acc);
        __syncthreads();
    }

    /* epilogue: bias + relu + store */
    const int r0 = rb * 128 + wm * 32 + (lane >> 2);
    const int c0 = cb * 128 + wn * 64 + (lane & 3) * 2;
#pragma unroll
    for (int mt = 0; mt < 2; mt++)
#pragma unroll
        for (int nt = 0; nt < 8; nt++) {
            const int cc = c0 + nt * 8;
            const float bx = b1[cc], by = b1[cc + 1];
            const int rr = r0 + mt * 16;
            float2 o0, o1;
            o0.x = fmaxf(acc[mt][nt][0] + bx, 0.f);
            o0.y = fmaxf(acc[mt][nt][1] + by, 0.f);
            o1.x = fmaxf(acc[mt][nt][2] + bx, 0.f);
            o1.y = fmaxf(acc[mt][nt][3] + by, 0.f);
            *(float2*)(g_H1 + (size_t)rr * Ff + cc)       = o0;
            *(float2*)(g_H1 + (size_t)(rr + 8) * Ff + cc) = o1;
        }
}

/* ------------------------------------------------------------------ */
/* K2: adj = sum_g wout[g]*relu((H1 @ W2^T)+b2) + bout */
__global__ __launch_bounds__(256)
void k_mlp2(const float* __restrict__ W2, const float* __restrict__ b2,
            const float* __restrict__ wout, const float* __restrict__ boutp,
            float* __restrict__ adj, int ppb, int full)
{
    __shared__ __align__(16) unsigned short smb[20480];
    __shared__ float red[128][2];

    const int tid = threadIdx.x, wid = tid >> 5, lane = tid & 31;
    const int wm = wid & 3, wn = wid >> 2;
    const int rb = blockIdx.x;
    const int srow = tid >> 1, sf4 = (tid & 1) * 4;
    const float* abase = g_H1 + (size_t)(rb * 128) * Ff;

    float part[2][2] = {{0.f, 0.f}, {0.f, 0.f}};

    for (int gc = 0; gc < 4; gc++) {
        const float* wbase = W2 + (size_t)(gc * 128) * Ff;
        float4 pa[4], pb[4];
#pragma unroll
        for (int q = 0; q < 4; q++) {
            pa[q] = *(const float4*)(abase + (size_t)srow * Ff + (sf4 + q) * 4);
            pb[q] = *(const float4*)(wbase + (size_t)srow * Ff + (sf4 + q) * 4);
        }
        float acc[2][8][4];
#pragma unroll
        for (int a = 0; a < 2; a++)
#pragma unroll
            for (int b = 0; b < 8; b++)
#pragma unroll
                for (int c = 0; c < 4; c++) acc[a][b][c] = 0.f;

        for (int c = 0; c < NCHUNK; c++) {
#pragma unroll
            for (int q = 0; q < 4; q++) {
                uint2 hi, lo;
                split4s(pa[q], hi, lo);
                int eo = srow * SSTRIDE + (sf4 + q) * 4;
                *(uint2*)((char*)smb + OF_AHI + eo*2) = hi;
                *(uint2*)((char*)smb + OF_ALO + eo*2) = lo;
                split4s(pb[q], hi, lo);
                *(uint2*)((char*)smb + OF_BHI + eo*2) = hi;
                *(uint2*)((char*)smb + OF_BLO + eo*2) = lo;
            }
            __syncthreads();
            if (c < NCHUNK - 1) {
                const int k0 = (c + 1) * KC;
#pragma unroll
                for (int q = 0; q < 4; q++) {
                    pa[q] = *(const float4*)(abase + (size_t)srow * Ff + k0 + (sf4 + q) * 4);
                    pb[q] = *(const float4*)(wbase + (size_t)srow * Ff + k0 + (sf4 + q) * 4);
                }
            }
            gemm_chunk(smb, wm, wn, lane, acc);
            __syncthreads();
        }

        /* fuse relu+wout into per-row partials */
        const int c0 = gc * 128 + wn * 64 + (lane & 3) * 2;
#pragma unroll
        for (int mt = 0; mt < 2; mt++)
#pragma unroll
            for (int nt = 0; nt < 8; nt++) {
                const int cc = c0 + nt * 8;
                const float bx = b2[cc], by = b2[cc + 1];
                const float wx = wout[cc], wy = wout[cc + 1];
                part[mt][0] += fmaxf(acc[mt][nt][0] + bx, 0.f) * wx
                             + fmaxf(acc[mt][nt][1] + by, 0.f) * wy;
                part[mt][1] += fmaxf(acc[mt][nt][2] + bx, 0.f) * wx
                             + fmaxf(acc[mt][nt][3] + by, 0.f) * wy;
            }
    }

    /* reduce over the 4 col-lanes (lane&3) */
#pragma unroll
    for (int mt = 0; mt < 2; mt++)
#pragma unroll
        for (int h = 0; h < 2; h++) {
            float v = part[mt][h];
            v += __shfl_xor_sync(0xffffffffu, v, 1);
            v += __shfl_xor_sync(0xffffffffu, v, 2);
            part[mt][h] = v;
        }
    if ((lane & 3) == 0) {
#pragma unroll
        for (int mt = 0; mt < 2; mt++)
#pragma unroll
            for (int h = 0; h < 2; h++)
                red[wm * 32 + mt * 16 + h * 8 + (lane >> 2)][wn] = part[mt][h];
    }
    __syncthreads();

    if (tid < 128) {
        float s = red[tid][0] + red[tid][1] + boutp[0];
        int gr = rb * 128 + tid;
        int b = gr / ppb, p = gr - b * ppb;
        int i, j;
        if (full) { i = c_pi[p]; j = c_pj[p]; } else { i = p; j = ZI; }
        adj[b * 121 + i * 11 + j] = s;
        adj[b * 121 + j * 11 + i] = s;
    }
}

/* ------------------------------------------------------------------ */
__global__ void k_softmax(const float* __restrict__ adj)
{
    int b = blockIdx.x;
    int t = threadIdx.x;
    float v = (t < 11) ? adj[b * 121 + ZI * 11 + t] : -1e30f;
    float m = v;
#pragma unroll
    for (int o = 16; o > 0; o >>= 1) m = fmaxf(m, __shfl_xor_sync(0xffffffffu, m, o));
    float e = (t < 11) ? expf(v - m) : 0.f;
    float s = e;
#pragma unroll
    for (int o = 16; o > 0; o >>= 1) s += __shfl_xor_sync(0xffffffffu, s, o);
    float a = e / s;
    if (t < 11) g_az[b * 12 + t] = a;
    if (t == ZI) g_az[b * 12 + 11] = a;
}

__global__ void k_mbase(const float* __restrict__ nf)
{
    int b = blockIdx.x;
    int f = blockIdx.y * 128 + threadIdx.x;
    float s = 0.f;
#pragma unroll
    for (int j = 0; j < 10; j++)
        s += g_az[b * 12 + j] * nf[(b * Nn + j) * Ff + f];
    g_mb[b * Ff + f] = s;
}

/* ------------------------------------------------------------------ */
/* K5: gi = m_z @ W_ih^T (z=0) ; gh = cur @ W_hh^T (z=1) */
__global__ __launch_bounds__(256)
void k_gru_mm(int colsel, const float* __restrict__ Wih, const float* __restrict__ Whh)
{
    __shared__ __align__(16) unsigned short smb[20480];
    __shared__ float azs[128];

    const int tid = threadIdx.x, wid = tid >> 5, lane = tid & 31;
    const int wm = wid & 3, wn = wid >> 2;
    const int rb = blockIdx.x, cb = blockIdx.y, wh = blockIdx.z;
    const float* cur = colptr(colsel);

    if (tid < 128) azs[tid] = g_az[(rb * 128 + tid) * 12 + 11];
    __syncthreads();

    const float* W = wh ? Whh : Wih;
    float* out = wh ? g_gh : g_gi;
    const float* wbase = W + (size_t)(cb * 128) * Ff;
    const int srow = tid >> 1, sf4 = (tid & 1) * 4;
    const size_t arow = (size_t)(rb * 128 + srow) * Ff;
    const float az = azs[srow];

    float4 pa[4], pb[4];
#pragma unroll
    for (int q = 0; q < 4; q++) {
        float4 cv = *(const float4*)(cur + arow + (sf4 + q) * 4);
        if (wh) pa[q] = cv;
        else {
            float4 mv = *(const float4*)(g_mb + arow + (sf4 + q) * 4);
            pa[q] = make_float4(mv.x + az*cv.x, mv.y + az*cv.y, mv.z + az*cv.z, mv.w + az*cv.w);
        }
        pb[q] = *(const float4*)(wbase + (size_t)srow * Ff + (sf4 + q) * 4);
    }

    float acc[2][8][4];
#pragma unroll
    for (int a = 0; a < 2; a++)
#pragma unroll
        for (int b = 0; b < 8; b++)
#pragma unroll
            for (int c = 0; c < 4; c++) acc[a][b][c] = 0.f;

    for (int c = 0; c < NCHUNK; c++) {
#pragma unroll
        for (int q = 0; q < 4; q++) {
            uint2 hi, lo;
            split4s(pa[q], hi, lo);
            int eo = srow * SSTRIDE + (sf4 + q) * 4;
            *(uint2*)((char*)smb + OF_AHI + eo*2) = hi;
            *(uint2*)((char*)smb + OF_ALO + eo*2) = lo;
            split4s(pb[q], hi, lo);
            *(uint2*)((char*)smb + OF_BHI + eo*2) = hi;
            *(uint2*)((char*)smb + OF_BLO + eo*2) = lo;
        }
        __syncthreads();
        if (c < NCHUNK - 1) {
            const int k0 = (c + 1) * KC;
#pragma unroll
            for (int q = 0; q < 4; q++) {
                float4 cv = *(const float4*)(cur + arow + k0 + (sf4 + q) * 4);
                if (wh) pa[q] = cv;
                else {
                    float4 mv = *(const float4*)(g_mb + arow + k0 + (sf4 + q) * 4);
                    pa[q] = make_float4(mv.x + az*cv.x, mv.y + az*cv.y, mv.z + az*cv.z, mv.w + az*cv.w);
                }
                pb[q] = *(const float4*)(wbase + (size_t)srow * Ff + k0 + (sf4 + q) * 4);
            }
        }
        gemm_chunk(smb, wm, wn, lane, acc);
        __syncthreads();
    }

    const int r0 = rb * 128 + wm * 32 + (lane >> 2);
    const int c0 = cb * 128 + wn * 64 + (lane & 3) * 2;
#pragma unroll
    for (int mt = 0; mt < 2; mt++)
#pragma unroll
        for (int nt = 0; nt < 8; nt++) {
            const int cc = c0 + nt * 8;
            const int rr = r0 + mt * 16;
            *(float2*)(out + (size_t)rr * G3 + cc)       = make_float2(acc[mt][nt][0], acc[mt][nt][1]);
            *(float2*)(out + (size_t)(rr + 8) * G3 + cc) = make_float2(acc[mt][nt][2], acc[mt][nt][3]);
        }
}

/* ------------------------------------------------------------------ */
__global__ void k_gate(int colsel)
{
    int idx = blockIdx.x * 256 + threadIdx.x;
    int b = idx >> 9, f = idx & 511;
    const float* cur = colptr(colsel);
    float* nxt = colptr(1 - colsel);
    const float* gib = g_gi + b * G3;
    const float* ghb = g_gh + b * G3;
    float ir = gib[f],         hr = ghb[f];
    float iz = gib[512 + f],   hz = ghb[512 + f];
    float in_ = gib[1024 + f], hn = ghb[1024 + f];
    float rr = 1.f / (1.f + expf(-(ir + hr)));
    float zz = 1.f / (1.f + expf(-(iz + hz)));
    float nn = tanhf(in_ + rr * hn);
    float h = cur[idx];
    nxt[idx] = (1.f - zz) * nn + zz * h;
}

__global__ void k_copy(int colsel, float* __restrict__ dst)
{
    int idx = blockIdx.x * 256 + threadIdx.x;
    dst[idx] = colptr(colsel)[idx];
}

/* ------------------------------------------------------------------ */
extern "C" void kernel_launch(void* const* d_in, const int* in_sizes, int n_in,
                              void* d_out, int out_size)
{
    const float* nf  = (const float*)d_in[0];
    const float* W1  = (const float*)d_in[1];
    const float* b1  = (const float*)d_in[2];
    const float* W2  = (const float*)d_in[3];
    const float* b2  = (const float*)d_in[4];
    const float* wo  = (const float*)d_in[5];
    const float* bo  = (const float*)d_in[6];
    const float* Wih = (const float*)d_in[7];
    const float* Whh = (const float*)d_in[8];

    float* adj    = (float*)d_out;
    float* colout = (float*)d_out + Bb * 121;

    k_init<<<(Bb * Ff) / 256, 256>>>(nf);

    int sel = 0;
    for (int t = 0; t < 3; t++) {
        if (t == 0) {
            k_mlp1<<<dim3(R0 / 128, Ff / 128), 256>>>(nf, sel, W1, b1, PPF, 1);
            k_mlp2<<<R0 / 128, 256>>>(W2, b2, wo, bo, adj, PPF, 1);
        } else {
            k_mlp1<<<dim3(R1 / 128, Ff / 128), 256>>>(nf, sel, W1, b1, Nn, 0);
            k_mlp2<<<R1 / 128, 256>>>(W2, b2, wo, bo, adj, Nn, 0);
        }
        k_softmax<<<Bb, 32>>>(adj);
        k_mbase<<<dim3(Bb, Ff / 128), 128>>>(nf);
        for (int s = 0; s < 3; s++) {
            k_gru_mm<<<dim3(Bb / 128, G3 / 128, 2), 256>>>(sel, Wih, Whh);
            k_gate<<<(Bb * Ff) / 256, 256>>>(sel);
            sel = 1 - sel;
        }
    }
    k_copy<<<(Bb * Ff) / 256, 256>>>(sel, colout);
}

// round 6
// speedup vs baseline: 2.3129x; 1.4624x over previous
#include <cuda_runtime.h>
#include <cuda_bf16.h>
#include <math.h>
#include <stdint.h>

#define Bb 1024
#define Nn 11
#define Ff 512
#define ZI 10
#define PPF 66
#define R0 (Bb*PPF)
#define R1 (Bb*Nn)
#define G3 1536

#define KC 32
#define NCHUNK (Ff/KC)          /* 16 */
#define SSTR 40                 /* bf16 elems per smem row (32 data + 8 pad) */
#define PL 10240                /* bytes per plane: 128*40*2 */
#define ST (4*PL)               /* bytes per stage (A_hi,A_lo,B_hi,B_lo) */
#define DSMEM (2*ST)            /* 81920 */

/* ------------------------------------------------------------------ */
__device__ __forceinline__ uint32_t smaddr(const void* p) {
    uint32_t a;
    asm("{ .reg .u64 t; cvta.to.shared.u64 t, %1; cvt.u32.u64 %0, t; }"
        : "=r"(a) : "l"(p));
    return a;
}
__device__ __forceinline__ void ldm4(uint32_t a, uint32_t* r) {
    asm volatile("ldmatrix.sync.aligned.m8n8.x4.shared.b16 {%0,%1,%2,%3}, [%4];"
                 : "=r"(r[0]), "=r"(r[1]), "=r"(r[2]), "=r"(r[3]) : "r"(a));
}
__device__ __forceinline__ void mma16816(float* d, const uint32_t* a, uint32_t b0, uint32_t b1) {
    asm volatile(
        "mma.sync.aligned.m16n8k16.row.col.f32.bf16.bf16.f32 "
        "{%0,%1,%2,%3},{%4,%5,%6,%7},{%8,%9},{%0,%1,%2,%3};"
        : "+f"(d[0]), "+f"(d[1]), "+f"(d[2]), "+f"(d[3])
        : "r"(a[0]), "r"(a[1]), "r"(a[2]), "r"(a[3]), "r"(b0), "r"(b1));
}
__device__ __forceinline__ void split1(float v, unsigned short& h, unsigned short& l) {
    __nv_bfloat16 bh = __float2bfloat16_rn(v);
    float r = v - __bfloat162float(bh);
    __nv_bfloat16 bl = __float2bfloat16_rn(r);
    h = *(unsigned short*)&bh;
    l = *(unsigned short*)&bl;
}

/* ------------------------------------------------------------------ */
__constant__ int c_pi[66] = {
  0,0,0,0,0,0,0,0,0,0,0, 1,1,1,1,1,1,1,1,1,1, 2,2,2,2,2,2,2,2,2,
  3,3,3,3,3,3,3,3, 4,4,4,4,4,4,4, 5,5,5,5,5,5, 6,6,6,6,6, 7,7,7,7, 8,8,8, 9,9, 10};
__constant__ int c_pj[66] = {
  0,1,2,3,4,5,6,7,8,9,10, 1,2,3,4,5,6,7,8,9,10, 2,3,4,5,6,7,8,9,10,
  3,4,5,6,7,8,9,10, 4,5,6,7,8,9,10, 5,6,7,8,9,10, 6,7,8,9,10, 7,8,9,10, 8,9,10, 9,10, 10};

/* f32 scratch */
__device__ float g_colA[Bb * Ff];
__device__ float g_colB[Bb * Ff];
__device__ float g_az[Bb * 12];
__device__ float g_mb[Bb * Ff];
__device__ float g_gi[Bb * G3];
__device__ float g_gh[Bb * G3];

/* pre-split bf16 operand planes (hi/lo) */
__device__ unsigned short g_W1h[Ff * Ff],  g_W1l[Ff * Ff];
__device__ unsigned short g_W2h[Ff * Ff],  g_W2l[Ff * Ff];
__device__ unsigned short g_Wihh[G3 * Ff], g_Wihl[G3 * Ff];
__device__ unsigned short g_Whhh[G3 * Ff], g_Whhl[G3 * Ff];
__device__ unsigned short g_Eh[R0 * Ff],   g_El[R0 * Ff];
__device__ unsigned short g_H1h[R0 * Ff],  g_H1l[R0 * Ff];
__device__ unsigned short g_czh[Bb * Ff],  g_czl[Bb * Ff];
__device__ unsigned short g_mzh[Bb * Ff],  g_mzl[Bb * Ff];

__device__ __forceinline__ float* colptr(int sel) { return sel ? g_colB : g_colA; }

/* ------------------------------------------------------------------ */
/* one 32-K chunk: 2 k16-steps, 3 split MMAs per (mt,nt) tile */
__device__ __forceinline__ void gemm_chunk2(uint32_t base, int wm, int wn,
                                            int lane, float acc[2][8][4])
{
    const int rsel = lane & 15;
    const int ksel = (lane >> 4) * 8;
#pragma unroll
    for (int s = 0; s < 2; s++) {
        uint32_t ah[2][4], al[2][4], bh[4][4], bl[4][4];
#pragma unroll
        for (int mt = 0; mt < 2; mt++) {
            uint32_t off = (uint32_t)((wm*32 + mt*16 + rsel) * SSTR + s*16 + ksel) * 2;
            ldm4(base + 0*PL + off, ah[mt]);
            ldm4(base + 1*PL + off, al[mt]);
        }
#pragma unroll
        for (int np = 0; np < 4; np++) {
            uint32_t off = (uint32_t)((wn*64 + np*16 + rsel) * SSTR + s*16 + ksel) * 2;
            ldm4(base + 2*PL + off, bh[np]);
            ldm4(base + 3*PL + off, bl[np]);
        }
#pragma unroll
        for (int mt = 0; mt < 2; mt++)
#pragma unroll
            for (int np = 0; np < 4; np++)
#pragma unroll
                for (int h = 0; h < 2; h++) {
                    const int nt = np*2 + h;
                    mma16816(acc[mt][nt], ah[mt], bh[np][h], bh[np][h+2]);
                    mma16816(acc[mt][nt], ah[mt], bl[np][h], bl[np][h+2]);
                    mma16816(acc[mt][nt], al[mt], bh[np][h], bh[np][h+2]);
                }
    }
}

/* double-buffered cp.async mainloop over K=512.
   A planes: row-major [128][Ff] bf16 at Ah/Al; B planes likewise Bh/Bl. */
__device__ __forceinline__ void gemm_pipe(
    const unsigned short* __restrict__ Ah, const unsigned short* __restrict__ Al,
    const unsigned short* __restrict__ Bh, const unsigned short* __restrict__ Bl,
    char* dsm, int tid, float acc[2][8][4])
{
    const uint32_t sb = smaddr(dsm);
    const int lane = tid & 31, wid = tid >> 5;
    const int wm = wid & 3, wn = wid >> 2;

    /* this thread's 8 transfers: 4 planes x 128 rows x 4 16B-quarters = 2048 */
    const unsigned short* sbase[8];
    uint32_t doff[8];
#pragma unroll
    for (int i = 0; i < 8; i++) {
        int id = tid + i * 256;
        int pl = id >> 9, w = id & 511, row = w >> 2, q = w & 3;
        const unsigned short* s0 = (pl == 0) ? Ah : (pl == 1) ? Al : (pl == 2) ? Bh : Bl;
        sbase[i] = s0 + (size_t)row * Ff + q * 8;
        doff[i] = (uint32_t)pl * PL + (uint32_t)(row * SSTR + q * 8) * 2;
    }

    auto stg = [&](int c, int s) {
        uint32_t db = sb + (uint32_t)s * ST;
#pragma unroll
        for (int i = 0; i < 8; i++)
            asm volatile("cp.async.ca.shared.global [%0],[%1],16;"
                         :: "r"(db + doff[i]), "l"(sbase[i] + c * KC) : "memory");
        asm volatile("cp.async.commit_group;" ::: "memory");
    };

    stg(0, 0);
    asm volatile("cp.async.wait_group 0;" ::: "memory");
    __syncthreads();
    for (int c = 0; c < NCHUNK; c++) {
        if (c + 1 < NCHUNK) stg(c + 1, (c + 1) & 1);
        gemm_chunk2(sb + (uint32_t)(c & 1) * ST, wm, wn, lane, acc);
        if (c + 1 < NCHUNK) asm volatile("cp.async.wait_group 0;" ::: "memory");
        __syncthreads();
    }
}

/* ------------------------------------------------------------------ */
__global__ void k_init(const float* __restrict__ nf)
{
    int idx = blockIdx.x * 256 + threadIdx.x;
    int b = idx >> 9, f = idx & 511;
    g_colA[idx] = nf[(b * Nn + ZI) * Ff + f];
}

/* split a dense f32 array into bf16 hi/lo planes (n multiple of 1024) */
__global__ void k_split_w(const float* __restrict__ src,
                          unsigned short* __restrict__ dh,
                          unsigned short* __restrict__ dl)
{
    int i4 = (blockIdx.x * 256 + threadIdx.x) * 4;
    float4 v = *(const float4*)(src + i4);
    ushort4 h, l;
    split1(v.x, h.x, l.x); split1(v.y, h.y, l.y);
    split1(v.z, h.z, l.z); split1(v.w, h.w, l.w);
    *(ushort4*)(dh + i4) = h;
    *(ushort4*)(dl + i4) = l;
}

/* E rows: E[r][f] = x_i[f]*x_j[f], pre-split */
__global__ void k_egen(const float* __restrict__ nf, int colsel, int ppb, int full)
{
    int t4 = blockIdx.x * 256 + threadIdx.x;   /* one per 4 elems */
    int r = t4 >> 7, q = t4 & 127;
    int b = r / ppb, p = r - b * ppb;
    int i, j;
    if (full) { i = c_pi[p]; j = c_pj[p]; } else { i = p; j = ZI; }
    const float* col = colptr(colsel);
    const float* xi = (i == ZI) ? (col + b * Ff) : (nf + (b * Nn + i) * Ff);
    const float* xj = (j == ZI) ? (col + b * Ff) : (nf + (b * Nn + j) * Ff);
    float4 a = *(const float4*)(xi + q * 4);
    float4 c2 = *(const float4*)(xj + q * 4);
    ushort4 h, l;
    split1(a.x * c2.x, h.x, l.x);
    split1(a.y * c2.y, h.y, l.y);
    split1(a.z * c2.z, h.z, l.z);
    split1(a.w * c2.w, h.w, l.w);
    size_t o = (size_t)r * Ff + q * 4;
    *(ushort4*)(g_Eh + o) = h;
    *(ushort4*)(g_El + o) = l;
}

/* ------------------------------------------------------------------ */
/* K1: H1 = relu(E @ W1^T + b1), output pre-split */
__global__ __launch_bounds__(256)
void k_mlp1(const float* __restrict__ b1)
{
    extern __shared__ char dsm[];
    const int tid = threadIdx.x, lane = tid & 31, wid = tid >> 5;
    const int wm = wid & 3, wn = wid >> 2;
    const int rb = blockIdx.x, cb = blockIdx.y;

    float acc[2][8][4];
#pragma unroll
    for (int a = 0; a < 2; a++)
#pragma unroll
        for (int b = 0; b < 8; b++)
#pragma unroll
            for (int c = 0; c < 4; c++) acc[a][b][c] = 0.f;

    gemm_pipe(g_Eh + (size_t)rb * 128 * Ff, g_El + (size_t)rb * 128 * Ff,
              g_W1h + (size_t)cb * 128 * Ff, g_W1l + (size_t)cb * 128 * Ff,
              dsm, tid, acc);

    const int r0 = rb * 128 + wm * 32 + (lane >> 2);
    const int c0 = cb * 128 + wn * 64 + (lane & 3) * 2;
#pragma unroll
    for (int mt = 0; mt < 2; mt++)
#pragma unroll
        for (int nt = 0; nt < 8; nt++) {
            const int cc = c0 + nt * 8;
            const float bx = b1[cc], by = b1[cc + 1];
#pragma unroll
            for (int hh = 0; hh < 2; hh++) {
                const int rr = r0 + mt * 16 + hh * 8;
                float v0 = fmaxf(acc[mt][nt][hh*2+0] + bx, 0.f);
                float v1 = fmaxf(acc[mt][nt][hh*2+1] + by, 0.f);
                ushort2 h, l;
                split1(v0, h.x, l.x);
                split1(v1, h.y, l.y);
                *(ushort2*)(g_H1h + (size_t)rr * Ff + cc) = h;
                *(ushort2*)(g_H1l + (size_t)rr * Ff + cc) = l;
            }
        }
}

/* ------------------------------------------------------------------ */
/* K2: adj = sum_g wout[g]*relu((H1 @ W2^T)+b2) + bout */
__global__ __launch_bounds__(256)
void k_mlp2(const float* __restrict__ b2, const float* __restrict__ wout,
            const float* __restrict__ boutp, float* __restrict__ adj,
            int ppb, int full)
{
    extern __shared__ char dsm[];
    __shared__ float red[128][2];

    const int tid = threadIdx.x, lane = tid & 31, wid = tid >> 5;
    const int wm = wid & 3, wn = wid >> 2;
    const int rb = blockIdx.x;

    float part[2][2] = {{0.f, 0.f}, {0.f, 0.f}};

    for (int gc = 0; gc < 4; gc++) {
        float acc[2][8][4];
#pragma unroll
        for (int a = 0; a < 2; a++)
#pragma unroll
            for (int b = 0; b < 8; b++)
#pragma unroll
                for (int c = 0; c < 4; c++) acc[a][b][c] = 0.f;

        gemm_pipe(g_H1h + (size_t)rb * 128 * Ff, g_H1l + (size_t)rb * 128 * Ff,
                  g_W2h + (size_t)gc * 128 * Ff, g_W2l + (size_t)gc * 128 * Ff,
                  dsm, tid, acc);

        const int c0 = gc * 128 + wn * 64 + (lane & 3) * 2;
#pragma unroll
        for (int mt = 0; mt < 2; mt++)
#pragma unroll
            for (int nt = 0; nt < 8; nt++) {
                const int cc = c0 + nt * 8;
                const float bx = b2[cc], by = b2[cc + 1];
                const float wx = wout[cc], wy = wout[cc + 1];
                part[mt][0] += fmaxf(acc[mt][nt][0] + bx, 0.f) * wx
                             + fmaxf(acc[mt][nt][1] + by, 0.f) * wy;
                part[mt][1] += fmaxf(acc[mt][nt][2] + bx, 0.f) * wx
                             + fmaxf(acc[mt][nt][3] + by, 0.f) * wy;
            }
    }

#pragma unroll
    for (int mt = 0; mt < 2; mt++)
#pragma unroll
        for (int h = 0; h < 2; h++) {
            float v = part[mt][h];
            v += __shfl_xor_sync(0xffffffffu, v, 1);
            v += __shfl_xor_sync(0xffffffffu, v, 2);
            part[mt][h] = v;
        }
    if ((lane & 3) == 0) {
#pragma unroll
        for (int mt = 0; mt < 2; mt++)
#pragma unroll
            for (int h = 0; h < 2; h++)
                red[wm * 32 + mt * 16 + h * 8 + (lane >> 2)][wn] = part[mt][h];
    }
    __syncthreads();

    if (tid < 128) {
        float s = red[tid][0] + red[tid][1] + boutp[0];
        int gr = rb * 128 + tid;
        int b = gr / ppb, p = gr - b * ppb;
        int i, j;
        if (full) { i = c_pi[p]; j = c_pj[p]; } else { i = p; j = ZI; }
        adj[b * 121 + i * 11 + j] = s;
        adj[b * 121 + j * 11 + i] = s;
    }
}

/* ------------------------------------------------------------------ */
__global__ void k_softmax(const float* __restrict__ adj)
{
    int b = blockIdx.x;
    int t = threadIdx.x;
    float v = (t < 11) ? adj[b * 121 + ZI * 11 + t] : -1e30f;
    float m = v;
#pragma unroll
    for (int o = 16; o > 0; o >>= 1) m = fmaxf(m, __shfl_xor_sync(0xffffffffu, m, o));
    float e = (t < 11) ? expf(v - m) : 0.f;
    float s = e;
#pragma unroll
    for (int o = 16; o > 0; o >>= 1) s += __shfl_xor_sync(0xffffffffu, s, o);
    float a = e / s;
    if (t < 11) g_az[b * 12 + t] = a;
    if (t == ZI) g_az[b * 12 + 11] = a;
}

__global__ void k_mbase(const float* __restrict__ nf)
{
    int b = blockIdx.x;
    int f = blockIdx.y * 128 + threadIdx.x;
    float s = 0.f;
#pragma unroll
    for (int j = 0; j < 10; j++)
        s += g_az[b * 12 + j] * nf[(b * Nn + j) * Ff + f];
    g_mb[b * Ff + f] = s;
}

/* split cur and m_z = mb + az*cur for the GRU GEMMs */
__global__ void k_prep(int colsel)
{
    int idx = blockIdx.x * 256 + threadIdx.x;   /* Bb*Ff */
    int b = idx >> 9;
    float cur = colptr(colsel)[idx];
    float az = g_az[b * 12 + 11];
    float mz = g_mb[idx] + az * cur;
    split1(cur, g_czh[idx], g_czl[idx]);
    split1(mz,  g_mzh[idx], g_mzl[idx]);
}

/* ------------------------------------------------------------------ */
/* K5: gi = m_z @ W_ih^T (z=0) ; gh = cur @ W_hh^T (z=1) */
__global__ __launch_bounds__(256)
void k_gru(void)
{
    extern __shared__ char dsm[];
    const int tid = threadIdx.x, lane = tid & 31, wid = tid >> 5;
    const int wm = wid & 3, wn = wid >> 2;
    const int rb = blockIdx.x, cb = blockIdx.y, wh = blockIdx.z;

    const unsigned short* Ah = (wh ? g_czh : g_mzh) + (size_t)rb * 128 * Ff;
    const unsigned short* Al = (wh ? g_czl : g_mzl) + (size_t)rb * 128 * Ff;
    const unsigned short* Bh = (wh ? g_Whhh : g_Wihh) + (size_t)cb * 128 * Ff;
    const unsigned short* Bl = (wh ? g_Whhl : g_Wihl) + (size_t)cb * 128 * Ff;
    float* out = wh ? g_gh : g_gi;

    float acc[2][8][4];
#pragma unroll
    for (int a = 0; a < 2; a++)
#pragma unroll
        for (int b = 0; b < 8; b++)
#pragma unroll
            for (int c = 0; c < 4; c++) acc[a][b][c] = 0.f;

    gemm_pipe(Ah, Al, Bh, Bl, dsm, tid, acc);

    const int r0 = rb * 128 + wm * 32 + (lane >> 2);
    const int c0 = cb * 128 + wn * 64 + (lane & 3) * 2;
#pragma unroll
    for (int mt = 0; mt < 2; mt++)
#pragma unroll
        for (int nt = 0; nt < 8; nt++) {
            const int cc = c0 + nt * 8;
            const int rr = r0 + mt * 16;
            *(float2*)(out + (size_t)rr * G3 + cc)       = make_float2(acc[mt][nt][0], acc[mt][nt][1]);
            *(float2*)(out + (size_t)(rr + 8) * G3 + cc) = make_float2(acc[mt][nt][2], acc[mt][nt][3]);
        }
}

/* ------------------------------------------------------------------ */
/* GRU gates; also produce the splits for the next step's GEMMs */
__global__ void k_gate(int colsel)
{
    int idx = blockIdx.x * 256 + threadIdx.x;
    int b = idx >> 9, f = idx & 511;
    const float* cur = colptr(colsel);
    float* nxt = colptr(1 - colsel);
    const float* gib = g_gi + b * G3;
    const float* ghb = g_gh + b * G3;
    float ir = gib[f],         hr = ghb[f];
    float iz = gib[512 + f],   hz = ghb[512 + f];
    float in_ = gib[1024 + f], hn = ghb[1024 + f];
    float rr = 1.f / (1.f + expf(-(ir + hr)));
    float zz = 1.f / (1.f + expf(-(iz + hz)));
    float nn = tanhf(in_ + rr * hn);
    float h = cur[idx];
    float v = (1.f - zz) * nn + zz * h;
    nxt[idx] = v;
    float az = g_az[b * 12 + 11];
    float mz = g_mb[idx] + az * v;
    split1(v,  g_czh[idx], g_czl[idx]);
    split1(mz, g_mzh[idx], g_mzl[idx]);
}

__global__ void k_copy(int colsel, float* __restrict__ dst)
{
    int idx = blockIdx.x * 256 + threadIdx.x;
    dst[idx] = colptr(colsel)[idx];
}

/* ------------------------------------------------------------------ */
extern "C" void kernel_launch(void* const* d_in, const int* in_sizes, int n_in,
                              void* d_out, int out_size)
{
    const float* nf  = (const float*)d_in[0];
    const float* W1  = (const float*)d_in[1];
    const float* b1  = (const float*)d_in[2];
    const float* W2  = (const float*)d_in[3];
    const float* b2  = (const float*)d_in[4];
    const float* wo  = (const float*)d_in[5];
    const float* bo  = (const float*)d_in[6];
    const float* Wih = (const float*)d_in[7];
    const float* Whh = (const float*)d_in[8];

    float* adj    = (float*)d_out;
    float* colout = (float*)d_out + Bb * 121;

    cudaFuncSetAttribute(k_mlp1, cudaFuncAttributeMaxDynamicSharedMemorySize, DSMEM);
    cudaFuncSetAttribute(k_mlp2, cudaFuncAttributeMaxDynamicSharedMemorySize, DSMEM);
    cudaFuncSetAttribute(k_gru,  cudaFuncAttributeMaxDynamicSharedMemorySize, DSMEM);

    unsigned short *w1h, *w1l, *w2h, *w2l, *wihh, *wihl, *whhh, *whhl;
    cudaGetSymbolAddress((void**)&w1h, g_W1h);   cudaGetSymbolAddress((void**)&w1l, g_W1l);
    cudaGetSymbolAddress((void**)&w2h, g_W2h);   cudaGetSymbolAddress((void**)&w2l, g_W2l);
    cudaGetSymbolAddress((void**)&wihh, g_Wihh); cudaGetSymbolAddress((void**)&wihl, g_Wihl);
    cudaGetSymbolAddress((void**)&whhh, g_Whhh); cudaGetSymbolAddress((void**)&whhl, g_Whhl);

    k_split_w<<<(Ff * Ff) / 1024, 256>>>(W1, w1h, w1l);
    k_split_w<<<(Ff * Ff) / 1024, 256>>>(W2, w2h, w2l);
    k_split_w<<<(G3 * Ff) / 1024, 256>>>(Wih, wihh, wihl);
    k_split_w<<<(G3 * Ff) / 1024, 256>>>(Whh, whhh, whhl);

    k_init<<<(Bb * Ff) / 256, 256>>>(nf);

    int sel = 0;
    for (int t = 0; t < 3; t++) {
        const int rows = (t == 0) ? R0 : R1;
        const int ppb  = (t == 0) ? PPF : Nn;
        const int full = (t == 0) ? 1 : 0;
        k_egen<<<(rows * (Ff / 4)) / 256, 256>>>(nf, sel, ppb, full);
        k_mlp1<<<dim3(rows / 128, 4), 256, DSMEM>>>(b1);
        k_mlp2<<<rows / 128, 256, DSMEM>>>(b2, wo, bo, adj, ppb, full);
        k_softmax<<<Bb, 32>>>(adj);
        k_mbase<<<dim3(Bb, Ff / 128), 128>>>(nf);
        k_prep<<<(Bb * Ff) / 256, 256>>>(sel);
        for (int s = 0; s < 3; s++) {
            k_gru<<<dim3(Bb / 128, G3 / 128, 2), 256, DSMEM>>>();
            k_gate<<<(Bb * Ff) / 256, 256>>>(sel);
            sel = 1 - sel;
        }
    }
    k_copy<<<(Bb * Ff) / 256, 256>>>(sel, colout);
}